// round 1
// baseline (speedup 1.0000x reference)
#include <cuda_runtime.h>
#include <cuda_bf16.h>

// Problem: bilinear (Luong "general") attention.
//   B=16, TQ=TK=DQ=DK=DV=1024
//   qW     = query @ W                      (16384 x 1024 x 1024 NN)
//   weight = qW @ keys^T + mask             (16x batched 1024^3 NT)
//   score  = softmax(weight, axis=-1)
//   ctx    = score @ values                 (16x batched 1024^3 NN)
// Output = concat(score, ctx) as f32.

#define BM 128
#define BN 128
#define BK 16
#define TM 8
#define TN 8
#define PAD 4
#define NDIM 1024
#define KDIM 1024

// Scratch for qW: 16384 x 1024 f32 = 64 MB (static device array: allocation-guard safe)
__device__ float g_qW[16777216];

template<bool TRANSB, bool ADDMASK>
__device__ __forceinline__ void gemm_body(const float* __restrict__ A,
                                          const float* __restrict__ B,
                                          const float* __restrict__ mask,
                                          float* __restrict__ C)
{
    __shared__ float As[BK][BM + PAD];
    __shared__ float Bs[BK][BN + PAD];

    const int tid = threadIdx.x;       // 0..255
    const int tx  = tid & 15;          // 16 thread-cols
    const int ty  = tid >> 4;          // 16 thread-rows
    const int blockRow = blockIdx.y * BM;
    const int blockCol = blockIdx.x * BN;

    // A-tile load geometry: 128 rows x 16 cols, one float4 per thread per half
    const int aR0 = tid >> 2;          // 0..63
    const int aC  = (tid & 3) << 2;    // 0,4,8,12
    const int aR1 = aR0 + 64;

    const float* Aptr0 = A + (size_t)(blockRow + aR0) * KDIM + aC;
    const float* Aptr1 = A + (size_t)(blockRow + aR1) * KDIM + aC;

    const float* Bptr0;
    const float* Bptr1;
    int bK0 = 0, bN0 = 0;
    if (TRANSB) {
        // B is [N, K] row-major; same tile geometry as A
        Bptr0 = B + (size_t)(blockCol + aR0) * KDIM + aC;
        Bptr1 = B + (size_t)(blockCol + aR1) * KDIM + aC;
    } else {
        // B is [K, N] row-major; 16 rows x 128 cols
        bK0 = tid >> 5;                // 0..7
        bN0 = (tid & 31) << 2;         // 0..124
        Bptr0 = B + (size_t)bK0 * NDIM + blockCol + bN0;
        Bptr1 = Bptr0 + (size_t)8 * NDIM;
    }

    // Prefetch tile 0 into registers
    float4 ra0 = *(const float4*)Aptr0;
    float4 ra1 = *(const float4*)Aptr1;
    float4 rb0 = *(const float4*)Bptr0;
    float4 rb1 = *(const float4*)Bptr1;

    float acc[TM][TN];
    #pragma unroll
    for (int i = 0; i < TM; i++)
        #pragma unroll
        for (int j = 0; j < TN; j++) acc[i][j] = 0.0f;

    for (int k0 = 0; k0 < KDIM; k0 += BK) {
        // Deposit prefetched tile into SMEM (A and NT-B stored transposed)
        As[aC+0][aR0] = ra0.x; As[aC+1][aR0] = ra0.y; As[aC+2][aR0] = ra0.z; As[aC+3][aR0] = ra0.w;
        As[aC+0][aR1] = ra1.x; As[aC+1][aR1] = ra1.y; As[aC+2][aR1] = ra1.z; As[aC+3][aR1] = ra1.w;
        if (TRANSB) {
            Bs[aC+0][aR0] = rb0.x; Bs[aC+1][aR0] = rb0.y; Bs[aC+2][aR0] = rb0.z; Bs[aC+3][aR0] = rb0.w;
            Bs[aC+0][aR1] = rb1.x; Bs[aC+1][aR1] = rb1.y; Bs[aC+2][aR1] = rb1.z; Bs[aC+3][aR1] = rb1.w;
        } else {
            *(float4*)&Bs[bK0    ][bN0] = rb0;
            *(float4*)&Bs[bK0 + 8][bN0] = rb1;
        }
        __syncthreads();

        // Prefetch next tile (overlaps with FMA work below)
        if (k0 + BK < KDIM) {
            Aptr0 += BK; Aptr1 += BK;
            if (TRANSB) { Bptr0 += BK; Bptr1 += BK; }
            else        { Bptr0 += (size_t)BK * NDIM; Bptr1 += (size_t)BK * NDIM; }
            ra0 = *(const float4*)Aptr0;
            ra1 = *(const float4*)Aptr1;
            rb0 = *(const float4*)Bptr0;
            rb1 = *(const float4*)Bptr1;
        }

        #pragma unroll
        for (int kk = 0; kk < BK; kk++) {
            float a[TM], b[TN];
            *(float4*)&a[0] = *(const float4*)&As[kk][ty * TM];
            *(float4*)&a[4] = *(const float4*)&As[kk][ty * TM + 4];
            *(float4*)&b[0] = *(const float4*)&Bs[kk][tx * TN];
            *(float4*)&b[4] = *(const float4*)&Bs[kk][tx * TN + 4];
            #pragma unroll
            for (int i = 0; i < TM; i++)
                #pragma unroll
                for (int j = 0; j < TN; j++)
                    acc[i][j] = fmaf(a[i], b[j], acc[i][j]);
        }
        __syncthreads();
    }

    #pragma unroll
    for (int i = 0; i < TM; i++) {
        size_t row = (size_t)(blockRow + ty * TM + i);
        #pragma unroll
        for (int j = 0; j < TN; j += 4) {
            int col = blockCol + tx * TN + j;
            float4 v;
            v.x = acc[i][j+0]; v.y = acc[i][j+1]; v.z = acc[i][j+2]; v.w = acc[i][j+3];
            if (ADDMASK) {
                v.x += mask[col+0]; v.y += mask[col+1];
                v.z += mask[col+2]; v.w += mask[col+3];
            }
            *(float4*)&C[row * NDIM + col] = v;
        }
    }
}

// GEMM1: qW = query @ W  (M=16384, one big NN GEMM; W shared across batch)
__global__ __launch_bounds__(256) void gemm_qw_kernel(const float* __restrict__ query,
                                                      const float* __restrict__ W)
{
    gemm_body<false, false>(query, W, nullptr, g_qW);
}

// GEMM2: logits = qW @ keys^T + mask  (batched NT), written into d_out score region
__global__ __launch_bounds__(256) void gemm_logits_kernel(const float* __restrict__ keys,
                                                          const float* __restrict__ mask,
                                                          float* __restrict__ score)
{
    size_t b = blockIdx.z;
    gemm_body<true, true>(g_qW + b * 1048576, keys + b * 1048576,
                          mask + b * 1024, score + b * 1048576);
}

// GEMM3: ctx = score @ values  (batched NN)
__global__ __launch_bounds__(256) void gemm_ctx_kernel(const float* __restrict__ score,
                                                       const float* __restrict__ values,
                                                       float* __restrict__ ctx)
{
    size_t b = blockIdx.z;
    gemm_body<false, false>(score + b * 1048576, values + b * 1048576,
                            nullptr, ctx + b * 1048576);
}

// In-place row softmax, row length 1024, 256 threads x 4 elems (float4 per thread)
__global__ __launch_bounds__(256) void softmax_kernel(float* __restrict__ S)
{
    __shared__ float red[8];
    size_t row = blockIdx.x;
    float4* p = reinterpret_cast<float4*>(S + row * 1024);
    int t = threadIdx.x;

    float4 v = p[t];
    float m = fmaxf(fmaxf(v.x, v.y), fmaxf(v.z, v.w));
    #pragma unroll
    for (int o = 16; o; o >>= 1) m = fmaxf(m, __shfl_xor_sync(0xffffffffu, m, o));
    if ((t & 31) == 0) red[t >> 5] = m;
    __syncthreads();
    m = red[0];
    #pragma unroll
    for (int i = 1; i < 8; i++) m = fmaxf(m, red[i]);

    v.x = expf(v.x - m); v.y = expf(v.y - m);
    v.z = expf(v.z - m); v.w = expf(v.w - m);
    float s = v.x + v.y + v.z + v.w;
    #pragma unroll
    for (int o = 16; o; o >>= 1) s += __shfl_xor_sync(0xffffffffu, s, o);
    __syncthreads();                 // red[] reuse guard
    if ((t & 31) == 0) red[t >> 5] = s;
    __syncthreads();
    s = red[0];
    #pragma unroll
    for (int i = 1; i < 8; i++) s += red[i];

    float inv = 1.0f / s;
    v.x *= inv; v.y *= inv; v.z *= inv; v.w *= inv;
    p[t] = v;
}

extern "C" void kernel_launch(void* const* d_in, const int* in_sizes, int n_in,
                              void* d_out, int out_size)
{
    (void)in_sizes; (void)n_in; (void)out_size;
    const float* query  = (const float*)d_in[0];   // [16,1024,1024]
    const float* keys   = (const float*)d_in[1];   // [16,1024,1024]
    const float* values = (const float*)d_in[2];   // [16,1024,1024]
    const float* W      = (const float*)d_in[3];   // [1024,1024]
    const float* mask   = (const float*)d_in[4];   // [16,1024]

    float* score = (float*)d_out;                         // [16,1024,1024]
    float* ctx   = score + (size_t)16 * 1024 * 1024;      // [16,1024,1024]

    // qW = query @ W    (M=16384 treated as one GEMM since W is batch-shared)
    gemm_qw_kernel<<<dim3(NDIM / BN, 16384 / BM, 1), 256>>>(query, W);

    // logits = qW @ keys^T + mask  -> score buffer
    gemm_logits_kernel<<<dim3(NDIM / BN, 1024 / BM, 16), 256>>>(keys, mask, score);

    // softmax in place over last dim
    softmax_kernel<<<16384, 256>>>(score);

    // ctx = score @ values
    gemm_ctx_kernel<<<dim3(NDIM / BN, 1024 / BM, 16), 256>>>(score, values, ctx);
}

// round 3
// speedup vs baseline: 1.4430x; 1.4430x over previous
#include <cuda_runtime.h>
#include <cstdint>

// Bilinear attention, B=16, T=D=1024:
//   qW = query @ W ; logits = qW @ keys^T + mask ; score = softmax(logits) ; ctx = score @ values
// GEMMs via mma.sync.m16n8k8 tf32 with 3-term error compensation
// (Ahi*Bhi + Ahi*Blo + Alo*Bhi), fp32 accumulate. PTX is sm_80-portable
// (tcgen05 is rejected by this build's .target sm_103).

#define NDIM 1024

// Scratch for qW: 16384 x 1024 f32 (static device array: allocation-guard safe)
__device__ float g_qW[16777216];

// ---- helpers -------------------------------------------------------------
static __device__ __forceinline__ uint32_t smem_u32(const void* p) {
    uint32_t a;
    asm("{ .reg .u64 t; cvta.to.shared.u64 t, %1; cvt.u32.u64 %0, t; }" : "=r"(a) : "l"(p));
    return a;
}
static __device__ __forceinline__ uint32_t f2tf32(float a) {
    uint32_t r;
    asm("cvt.rna.tf32.f32 %0, %1;" : "=r"(r) : "f"(a));
    return r;
}
// split f32 -> tf32 hi + tf32 lo (bit patterns ready for mma operands)
static __device__ __forceinline__ void splitu(float a, uint32_t& h, uint32_t& l) {
    h = f2tf32(a);
    l = f2tf32(a - __uint_as_float(h));
}
static __device__ __forceinline__ void cpa16(uint32_t dst, const void* src) {
    asm volatile("cp.async.ca.shared.global [%0], [%1], 16;" :: "r"(dst), "l"(src));
}
static __device__ __forceinline__ void cp_commit() {
    asm volatile("cp.async.commit_group;" ::: "memory");
}
static __device__ __forceinline__ void cp_wait2() {
    asm volatile("cp.async.wait_group 2;" ::: "memory");
}
static __device__ __forceinline__ void mma8(float* d, const uint32_t* a, const uint32_t* b) {
    asm volatile(
        "mma.sync.aligned.m16n8k8.row.col.f32.tf32.tf32.f32 "
        "{%0,%1,%2,%3}, {%4,%5,%6,%7}, {%8,%9}, {%0,%1,%2,%3};"
        : "+f"(d[0]), "+f"(d[1]), "+f"(d[2]), "+f"(d[3])
        : "r"(a[0]), "r"(a[1]), "r"(a[2]), "r"(a[3]), "r"(b[0]), "r"(b[1]));
}

// ---- SMEM layout (raw f32 tiles, 3 stages) -------------------------------
// Stage: A 128x16 at stride 20 (2560 f), B 2560 f (NT: 128x16 @20, NN: 16x128 @136)
#define STAGES 3
#define A_OFF(s) ((s) * 5120)
#define B_OFF(s) ((s) * 5120 + 2560)
static constexpr int SMEM_BYTES = STAGES * 5120 * 4;   // 61440

template<bool TRANSB, bool ADDMASK>
__global__ __launch_bounds__(128) void gemm_tc_kernel(
    const float* __restrict__ A, const float* __restrict__ B,
    float* __restrict__ C, const float* __restrict__ mask,
    size_t sA, size_t sB, size_t sC)
{
    extern __shared__ float sm[];
    const uint32_t su = smem_u32(sm);
    const int tid = threadIdx.x, wid = tid >> 5, lid = tid & 31;
    const int g = lid >> 2, tg = lid & 3;        // mma group / thread-in-group
    const int wm = (wid >> 1) * 64, wn = (wid & 1) * 64;
    const int M0 = blockIdx.y * 128, N0 = blockIdx.x * 128;
    const size_t b = blockIdx.z;
    A += b * sA; B += b * sB; C += b * sC;
    const float* mp = ADDMASK ? (mask + b * 1024) : nullptr;

    // producer geometry (per-thread: 4 x cp.async 16B for A, 4 for B)
    const int ar = tid >> 2, acol = (tid & 3) << 2;   // A & NT-B: rows 0..31(+32p), 16-col rows
    const int bkr = tid >> 3, bcol = (tid & 7) << 4;  // NN-B: 16 rows x 128 cols

    float acc[4][8][4];
    #pragma unroll
    for (int mi = 0; mi < 4; mi++)
        #pragma unroll
        for (int ni = 0; ni < 8; ni++)
            #pragma unroll
            for (int r = 0; r < 4; r++) acc[mi][ni][r] = 0.0f;

    // issue chunk c (k-range [16c, 16c+16)) into stage st
    auto issue = [&](int c) {
        const int st = c % STAGES;
        const int k0 = c << 4;
        #pragma unroll
        for (int p = 0; p < 4; p++) {
            cpa16(su + (A_OFF(st) + (ar + 32 * p) * 20 + acol) * 4,
                  A + (size_t)(M0 + ar + 32 * p) * NDIM + k0 + acol);
        }
        if (TRANSB) {
            #pragma unroll
            for (int p = 0; p < 4; p++)
                cpa16(su + (B_OFF(st) + (ar + 32 * p) * 20 + acol) * 4,
                      B + (size_t)(N0 + ar + 32 * p) * NDIM + k0 + acol);
        } else {
            #pragma unroll
            for (int p = 0; p < 4; p++)
                cpa16(su + (B_OFF(st) + bkr * 136 + bcol + 4 * p) * 4,
                      B + (size_t)(k0 + bkr) * NDIM + N0 + bcol + 4 * p);
        }
        cp_commit();
    };

    issue(0);
    issue(1);

    for (int c = 0; c < 64; c++) {
        if (c + 2 < 64) issue(c + 2); else cp_commit();   // keep group accounting uniform
        cp_wait2();
        __syncthreads();

        const float* As = sm + A_OFF(c % STAGES);
        const float* Bs = sm + B_OFF(c % STAGES);
        #pragma unroll
        for (int ks = 0; ks < 16; ks += 8) {
            uint32_t ah[4][4], al[4][4], bh[8][2], bl[8][2];
            #pragma unroll
            for (int mi = 0; mi < 4; mi++) {
                const int r0 = wm + mi * 16 + g;
                const int c0 = ks + tg;
                splitu(As[r0 * 20 + c0],           ah[mi][0], al[mi][0]);
                splitu(As[(r0 + 8) * 20 + c0],     ah[mi][1], al[mi][1]);
                splitu(As[r0 * 20 + c0 + 4],       ah[mi][2], al[mi][2]);
                splitu(As[(r0 + 8) * 20 + c0 + 4], ah[mi][3], al[mi][3]);
            }
            #pragma unroll
            for (int ni = 0; ni < 8; ni++) {
                const int n0 = wn + ni * 8 + g;
                if (TRANSB) {
                    splitu(Bs[n0 * 20 + ks + tg],     bh[ni][0], bl[ni][0]);
                    splitu(Bs[n0 * 20 + ks + tg + 4], bh[ni][1], bl[ni][1]);
                } else {
                    splitu(Bs[(ks + tg) * 136 + n0],     bh[ni][0], bl[ni][0]);
                    splitu(Bs[(ks + tg + 4) * 136 + n0], bh[ni][1], bl[ni][1]);
                }
            }
            #pragma unroll
            for (int mi = 0; mi < 4; mi++)
                #pragma unroll
                for (int ni = 0; ni < 8; ni++) {
                    mma8(acc[mi][ni], ah[mi], bh[ni]);
                    mma8(acc[mi][ni], ah[mi], bl[ni]);
                    mma8(acc[mi][ni], al[mi], bh[ni]);
                }
        }
        __syncthreads();
    }

    // epilogue: d0,d1 at (g, 2tg..2tg+1), d2,d3 at (g+8, ...)
    #pragma unroll
    for (int mi = 0; mi < 4; mi++) {
        #pragma unroll
        for (int ni = 0; ni < 8; ni++) {
            const int r0 = M0 + wm + mi * 16 + g;
            const int cc = N0 + wn + ni * 8 + 2 * tg;
            float2 v0 = make_float2(acc[mi][ni][0], acc[mi][ni][1]);
            float2 v1 = make_float2(acc[mi][ni][2], acc[mi][ni][3]);
            if (ADDMASK) {
                const float m0v = mp[cc], m1v = mp[cc + 1];
                v0.x += m0v; v0.y += m1v;
                v1.x += m0v; v1.y += m1v;
            }
            *(float2*)(C + (size_t)r0 * NDIM + cc)       = v0;
            *(float2*)(C + (size_t)(r0 + 8) * NDIM + cc) = v1;
        }
    }
}

// In-place row softmax, row length 1024
__global__ __launch_bounds__(256) void softmax_kernel(float* __restrict__ S)
{
    __shared__ float red[8];
    size_t row = blockIdx.x;
    float4* p = reinterpret_cast<float4*>(S + row * 1024);
    int t = threadIdx.x;

    float4 v = p[t];
    float m = fmaxf(fmaxf(v.x, v.y), fmaxf(v.z, v.w));
    #pragma unroll
    for (int o = 16; o; o >>= 1) m = fmaxf(m, __shfl_xor_sync(0xffffffffu, m, o));
    if ((t & 31) == 0) red[t >> 5] = m;
    __syncthreads();
    m = red[0];
    #pragma unroll
    for (int i = 1; i < 8; i++) m = fmaxf(m, red[i]);

    v.x = expf(v.x - m); v.y = expf(v.y - m);
    v.z = expf(v.z - m); v.w = expf(v.w - m);
    float s = v.x + v.y + v.z + v.w;
    #pragma unroll
    for (int o = 16; o; o >>= 1) s += __shfl_xor_sync(0xffffffffu, s, o);
    __syncthreads();
    if ((t & 31) == 0) red[t >> 5] = s;
    __syncthreads();
    s = red[0];
    #pragma unroll
    for (int i = 1; i < 8; i++) s += red[i];

    float inv = 1.0f / s;
    v.x *= inv; v.y *= inv; v.z *= inv; v.w *= inv;
    p[t] = v;
}

extern "C" void kernel_launch(void* const* d_in, const int* in_sizes, int n_in,
                              void* d_out, int out_size)
{
    (void)in_sizes; (void)n_in; (void)out_size;
    const float* query  = (const float*)d_in[0];   // [16,1024,1024]
    const float* keys   = (const float*)d_in[1];   // [16,1024,1024]
    const float* values = (const float*)d_in[2];   // [16,1024,1024]
    const float* W      = (const float*)d_in[3];   // [1024,1024]
    const float* mask   = (const float*)d_in[4];   // [16,1024]

    float* score = (float*)d_out;                        // [16,1024,1024]
    float* ctx   = score + (size_t)16 * 1024 * 1024;     // [16,1024,1024]

    cudaFuncSetAttribute(gemm_tc_kernel<false, false>,
                         cudaFuncAttributeMaxDynamicSharedMemorySize, SMEM_BYTES);
    cudaFuncSetAttribute(gemm_tc_kernel<true, true>,
                         cudaFuncAttributeMaxDynamicSharedMemorySize, SMEM_BYTES);

    float* qW;
    cudaGetSymbolAddress((void**)&qW, g_qW);

    // qW = query @ W : one 16384x1024x1024 NN GEMM (W batch-shared, no transpose needed)
    gemm_tc_kernel<false, false><<<dim3(8, 128, 1), 128, SMEM_BYTES>>>(
        query, W, qW, nullptr, 0, 0, 0);

    // logits = qW @ keys^T + mask -> score  (NT: keys is [N,K] row-major)
    gemm_tc_kernel<true, true><<<dim3(8, 8, 16), 128, SMEM_BYTES>>>(
        qW, keys, score, mask, 1048576, 1048576, 1048576);

    // softmax in place over last dim
    softmax_kernel<<<16384, 256>>>(score);

    // ctx = score @ values  (NN: values is [K,N] row-major)
    gemm_tc_kernel<false, false><<<dim3(8, 8, 16), 128, SMEM_BYTES>>>(
        score, values, ctx, nullptr, 1048576, 1048576, 1048576);
}